// round 2
// baseline (speedup 1.0000x reference)
#include <cuda_runtime.h>
#include <math.h>

#define EMB     512
#define DIN     1024
#define DSTATE  128
#define NH      16
#define HDIM    64
#define CDIM    1280
#define DPROJ   2320
#define BATCH   32
#define SEQ     2048
#define NTOK    (BATCH * SEQ)
#define EPSN    1e-5f

// ---------------- scratch (device globals; no runtime allocation) ----------------
static __device__ float g_zn  [(size_t)NTOK * EMB];    // 134 MB
static __device__ float g_proj[(size_t)NTOK * DPROJ];  // 608 MB
static __device__ float g_xbc [(size_t)NTOK * CDIM];   // 336 MB
static __device__ float g_dt  [(size_t)NTOK * NH];     // 4 MB
static __device__ float g_dA  [(size_t)NTOK * NH];     // 4 MB
static __device__ float g_y   [(size_t)NTOK * DIN];    // 268 MB
static __device__ float g_wc  [EMB * DIN];
static __device__ float g_s   [EMB];

// ---------------- LayerNorm over EMB=512 ----------------
__global__ void ln_kernel(const float* __restrict__ z, const float* __restrict__ w,
                          const float* __restrict__ b, float* __restrict__ out)
{
    const int row = blockIdx.x;
    const int tid = threadIdx.x;  // 128 threads, 4 floats each
    float4 v = ((const float4*)(z + (size_t)row * EMB))[tid];
    float s  = v.x + v.y + v.z + v.w;
    float sq = v.x*v.x + v.y*v.y + v.z*v.z + v.w*v.w;
#pragma unroll
    for (int m = 16; m; m >>= 1) {
        s  += __shfl_xor_sync(0xffffffffu, s,  m);
        sq += __shfl_xor_sync(0xffffffffu, sq, m);
    }
    __shared__ float sh[8];
    if ((tid & 31) == 0) { sh[tid >> 5] = s; sh[4 + (tid >> 5)] = sq; }
    __syncthreads();
    s  = sh[0] + sh[1] + sh[2] + sh[3];
    sq = sh[4] + sh[5] + sh[6] + sh[7];
    const float mean = s * (1.f / EMB);
    const float var  = sq * (1.f / EMB) - mean * mean;
    const float r    = rsqrtf(var + EPSN);
    float4 w4 = ((const float4*)w)[tid];
    float4 b4 = ((const float4*)b)[tid];
    float4 o;
    o.x = (v.x - mean) * r * w4.x + b4.x;
    o.y = (v.y - mean) * r * w4.y + b4.y;
    o.z = (v.z - mean) * r * w4.z + b4.z;
    o.w = (v.w - mean) * r * w4.w + b4.w;
    ((float4*)(out + (size_t)row * EMB))[tid] = o;
}

// ---------------- generic SGEMM: C[M,N] = A[M,K] * B[N,K]^T (+bias +resid) ----------------
// 128x128 tile, BK=16, 256 threads, 8x8 microtile, global->register prefetch.
// M must be a multiple of 128, K a multiple of 16. N-edge guarded.
__global__ __launch_bounds__(256, 2)
void sgemm_nt(const float* __restrict__ A, const float* __restrict__ B,
              float* __restrict__ C, int M, int N, int K,
              const float* __restrict__ bias, const float* __restrict__ resid)
{
    __shared__ float As[16][132];
    __shared__ float Bs[16][132];
    const int tid  = threadIdx.x;
    const int bm   = blockIdx.y << 7;
    const int bn   = blockIdx.x << 7;
    const int row0 = (tid >> 4) << 3;
    const int col0 = (tid & 15) << 3;

    float acc[8][8];
#pragma unroll
    for (int i = 0; i < 8; i++)
#pragma unroll
        for (int j = 0; j < 8; j++) acc[i][j] = 0.f;

    const int lr = tid >> 2;        // 0..63
    const int lk = (tid & 3) << 2;  // 0,4,8,12

    // preload first k-tile
    float4 pa[2], pb[2];
#pragma unroll
    for (int it = 0; it < 2; it++) {
        const int r = lr + (it << 6);
        pa[it] = *(const float4*)(A + (size_t)(bm + r) * K + lk);
        pb[it] = make_float4(0.f, 0.f, 0.f, 0.f);
        if (bn + r < N)
            pb[it] = *(const float4*)(B + (size_t)(bn + r) * K + lk);
    }

    for (int k0 = 0; k0 < K; k0 += 16) {
        // stage current tile to smem
#pragma unroll
        for (int it = 0; it < 2; it++) {
            const int r = lr + (it << 6);
            As[lk+0][r] = pa[it].x; As[lk+1][r] = pa[it].y;
            As[lk+2][r] = pa[it].z; As[lk+3][r] = pa[it].w;
            Bs[lk+0][r] = pb[it].x; Bs[lk+1][r] = pb[it].y;
            Bs[lk+2][r] = pb[it].z; Bs[lk+3][r] = pb[it].w;
        }
        __syncthreads();

        // prefetch next tile into registers (overlaps with the FFMA block below)
        if (k0 + 16 < K) {
#pragma unroll
            for (int it = 0; it < 2; it++) {
                const int r = lr + (it << 6);
                pa[it] = *(const float4*)(A + (size_t)(bm + r) * K + k0 + 16 + lk);
                pb[it] = make_float4(0.f, 0.f, 0.f, 0.f);
                if (bn + r < N)
                    pb[it] = *(const float4*)(B + (size_t)(bn + r) * K + k0 + 16 + lk);
            }
        }

#pragma unroll
        for (int kk = 0; kk < 16; kk++) {
            float a[8], b[8];
            *(float4*)&a[0] = *(const float4*)&As[kk][row0];
            *(float4*)&a[4] = *(const float4*)&As[kk][row0 + 4];
            *(float4*)&b[0] = *(const float4*)&Bs[kk][col0];
            *(float4*)&b[4] = *(const float4*)&Bs[kk][col0 + 4];
#pragma unroll
            for (int i = 0; i < 8; i++)
#pragma unroll
                for (int j = 0; j < 8; j++)
                    acc[i][j] = fmaf(a[i], b[j], acc[i][j]);
        }
        __syncthreads();
    }
#pragma unroll
    for (int i = 0; i < 8; i++) {
        const size_t mrow = (size_t)(bm + row0 + i) * N;
#pragma unroll
        for (int j = 0; j < 8; j++) {
            const int n = bn + col0 + j;
            if (n < N) {
                float v = acc[i][j];
                if (bias)  v += bias[n];
                if (resid) v += resid[mrow + n];
                C[mrow + n] = v;
            }
        }
    }
}

// ---------------- dt = softplus(proj[..,2304+h] + dt_bias); dA = exp(dt * -exp(A_log)) ----------------
__global__ void dt_kernel(const float* __restrict__ proj, const float* __restrict__ dtb,
                          const float* __restrict__ alog, float* __restrict__ dt,
                          float* __restrict__ dA)
{
    const int i = blockIdx.x * 256 + threadIdx.x;
    if (i >= NTOK * NH) return;
    const int h   = i & (NH - 1);
    const int row = i >> 4;
    const float v = proj[(size_t)row * DPROJ + (DIN + CDIM) + h] + dtb[h];
    const float d = (v > 20.f) ? v : log1pf(expf(v));
    dt[i] = d;
    dA[i] = expf(-d * expf(alog[h]));
}

// ---------------- depthwise causal conv (width 4) + bias + SiLU ----------------
__global__ void conv_kernel(const float* __restrict__ proj, const float* __restrict__ cw,
                            const float* __restrict__ cb, float* __restrict__ xbc)
{
    const int idx = blockIdx.x * 256 + threadIdx.x;   // NTOK*CDIM total
    const int c   = idx % CDIM;
    const int bt  = idx / CDIM;
    const int t   = bt & (SEQ - 1);
    float acc = cb[c];
#pragma unroll
    for (int d = 0; d < 4; d++) {
        if (t - d >= 0)
            acc = fmaf(proj[(size_t)(bt - d) * DPROJ + DIN + c], cw[c * 4 + (3 - d)], acc);
    }
    xbc[idx] = acc / (1.f + expf(-acc));   // silu
}

// ---------------- SSM scan: one CTA per (batch, head) ----------------
// thread (p4 = tid>>4, ng = tid&15) owns h[p4*4 .. +3][n = ng + 16*j, j<8] (32 state cells).
// Strided n so smem B/C reads are bank-conflict-free. Double-buffered step inputs,
// one __syncthreads per step. y-reduction over the 16 ng lanes via shfl_xor.
__global__ __launch_bounds__(256, 4)
void scan_kernel(const float* __restrict__ xbc, const float* __restrict__ dt,
                 const float* __restrict__ dA, const float* __restrict__ Dp,
                 float* __restrict__ y)
{
    const int b   = blockIdx.x >> 4;
    const int hd  = blockIdx.x & 15;
    const int tid = threadIdx.x;
    const int p4  = tid >> 4;
    const int ng  = tid & 15;
    __shared__ float sB[2][DSTATE], sC[2][DSTATE], sx[2][HDIM];
    __shared__ float sdt[2], sdA[2];

    float h[4][8];
#pragma unroll
    for (int i = 0; i < 4; i++)
#pragma unroll
        for (int j = 0; j < 8; j++) h[i][j] = 0.f;

    const float  Dh = Dp[hd];
    const size_t rb = (size_t)b * SEQ;
    {
        const float* p = xbc + rb * CDIM;
        if (tid < 128) { sB[0][tid] = p[DIN + tid]; sC[0][tid] = p[DIN + DSTATE + tid]; }
        if (tid < 64)  sx[0][tid] = p[hd * HDIM + tid];
        if (tid == 0)  { sdt[0] = dt[rb * NH + hd]; sdA[0] = dA[rb * NH + hd]; }
    }
    __syncthreads();

    for (int t = 0; t < SEQ; t++) {
        const int cur = t & 1, nxt = cur ^ 1;
        if (t + 1 < SEQ) {
            const float* p = xbc + (rb + t + 1) * CDIM;
            if (tid < 128) { sB[nxt][tid] = p[DIN + tid]; sC[nxt][tid] = p[DIN + DSTATE + tid]; }
            if (tid < 64)  sx[nxt][tid] = p[hd * HDIM + tid];
            if (tid == 0)  { sdt[nxt] = dt[(rb + t + 1) * NH + hd];
                             sdA[nxt] = dA[(rb + t + 1) * NH + hd]; }
        }
        const float dtv = sdt[cur], dAv = sdA[cur];
        const float4 xv = *(const float4*)&sx[cur][p4 << 2];
        const float c0 = dtv * xv.x, c1 = dtv * xv.y, c2 = dtv * xv.z, c3 = dtv * xv.w;
        float a0 = 0.f, a1 = 0.f, a2 = 0.f, a3 = 0.f;
#pragma unroll
        for (int j = 0; j < 8; j++) {
            const int   n  = ng + (j << 4);
            const float Bv = sB[cur][n];
            const float Cv = sC[cur][n];
            h[0][j] = fmaf(h[0][j], dAv, c0 * Bv);  a0 = fmaf(h[0][j], Cv, a0);
            h[1][j] = fmaf(h[1][j], dAv, c1 * Bv);  a1 = fmaf(h[1][j], Cv, a1);
            h[2][j] = fmaf(h[2][j], dAv, c2 * Bv);  a2 = fmaf(h[2][j], Cv, a2);
            h[3][j] = fmaf(h[3][j], dAv, c3 * Bv);  a3 = fmaf(h[3][j], Cv, a3);
        }
#pragma unroll
        for (int m = 1; m < 16; m <<= 1) {
            a0 += __shfl_xor_sync(0xffffffffu, a0, m);
            a1 += __shfl_xor_sync(0xffffffffu, a1, m);
            a2 += __shfl_xor_sync(0xffffffffu, a2, m);
            a3 += __shfl_xor_sync(0xffffffffu, a3, m);
        }
        if (ng == 0) {
            float4 o;
            o.x = a0 + xv.x * Dh;
            o.y = a1 + xv.y * Dh;
            o.z = a2 + xv.z * Dh;
            o.w = a3 + xv.w * Dh;
            *(float4*)(y + (rb + t) * (size_t)DIN + hd * HDIM + (p4 << 2)) = o;
        }
        __syncthreads();
    }
}

// ---------------- y = y*silu(zg); RMSNorm over DIN (in place) ----------------
__global__ void gate_rms_kernel(float* __restrict__ y, const float* __restrict__ proj,
                                const float* __restrict__ nw)
{
    const int row = blockIdx.x;
    const int tid = threadIdx.x;  // 256 threads, float4 each
    float4 yv = *(float4*)(y + (size_t)row * DIN + (tid << 2));
    float4 zg = *(const float4*)(proj + (size_t)row * DPROJ + (tid << 2));
    float4 g;
    g.x = yv.x * (zg.x / (1.f + expf(-zg.x)));
    g.y = yv.y * (zg.y / (1.f + expf(-zg.y)));
    g.z = yv.z * (zg.z / (1.f + expf(-zg.z)));
    g.w = yv.w * (zg.w / (1.f + expf(-zg.w)));
    float sq = g.x*g.x + g.y*g.y + g.z*g.z + g.w*g.w;
#pragma unroll
    for (int m = 16; m; m >>= 1) sq += __shfl_xor_sync(0xffffffffu, sq, m);
    __shared__ float sh[8];
    if ((tid & 31) == 0) sh[tid >> 5] = sq;
    __syncthreads();
    const float tot = sh[0] + sh[1] + sh[2] + sh[3] + sh[4] + sh[5] + sh[6] + sh[7];
    const float r   = rsqrtf(tot * (1.f / DIN) + EPSN);
    float4 w4 = ((const float4*)nw)[tid];
    float4 o;
    o.x = g.x * r * w4.x; o.y = g.y * r * w4.y; o.z = g.z * r * w4.z; o.w = g.w * r * w4.w;
    *(float4*)(y + (size_t)row * DIN + (tid << 2)) = o;
}

// ---------------- s[e] = ff_g[e] / ||ff_v[e,:]|| (one warp per row) ----------------
__global__ void wnorm_kernel(const float* __restrict__ fv, const float* __restrict__ fg,
                             float* __restrict__ s)
{
    const int e   = blockIdx.x * 8 + (threadIdx.x >> 5);
    const int lid = threadIdx.x & 31;
    const float* rp = fv + (size_t)e * EMB;
    float sq = 0.f;
    for (int k = lid; k < EMB; k += 32) { const float v = rp[k]; sq += v * v; }
#pragma unroll
    for (int m = 16; m; m >>= 1) sq += __shfl_xor_sync(0xffffffffu, sq, m);
    if (lid == 0) s[e] = fg[e] / sqrtf(sq);
}

// ---------------- Wc[e,j] = s[e] * sum_k ff_v[e,k] * out_proj_w[k,j] ----------------
__global__ void wc_kernel(const float* __restrict__ fv, const float* __restrict__ s,
                          const float* __restrict__ op, float* __restrict__ wc)
{
    const int j = blockIdx.x * 256 + threadIdx.x;  // 0..DIN-1
    const int e = blockIdx.y;
    const float* fr = fv + (size_t)e * EMB;
    float acc = 0.f;
#pragma unroll 4
    for (int k = 0; k < EMB; k++)
        acc = fmaf(fr[k], op[(size_t)k * DIN + j], acc);
    wc[(size_t)e * DIN + j] = acc * s[e];
}

// ---------------- launch ----------------
extern "C" void kernel_launch(void* const* d_in, const int* in_sizes, int n_in,
                              void* d_out, int out_size)
{
    const float* z    = (const float*)d_in[0];
    const float* ln_w = (const float*)d_in[1];
    const float* ln_b = (const float*)d_in[2];
    const float* ipw  = (const float*)d_in[3];
    const float* cw   = (const float*)d_in[4];
    const float* cb   = (const float*)d_in[5];
    const float* dtb  = (const float*)d_in[6];
    const float* alog = (const float*)d_in[7];
    const float* Dp   = (const float*)d_in[8];
    const float* nw   = (const float*)d_in[9];
    const float* opw  = (const float*)d_in[10];
    const float* ffv  = (const float*)d_in[11];
    const float* ffg  = (const float*)d_in[12];
    const float* ffb  = (const float*)d_in[13];
    float* out = (float*)d_out;
    (void)in_sizes; (void)n_in; (void)out_size;

    float *zn, *proj, *xbc, *dtp, *dAp, *yp, *wcp, *sp;
    cudaGetSymbolAddress((void**)&zn,   g_zn);
    cudaGetSymbolAddress((void**)&proj, g_proj);
    cudaGetSymbolAddress((void**)&xbc,  g_xbc);
    cudaGetSymbolAddress((void**)&dtp,  g_dt);
    cudaGetSymbolAddress((void**)&dAp,  g_dA);
    cudaGetSymbolAddress((void**)&yp,   g_y);
    cudaGetSymbolAddress((void**)&wcp,  g_wc);
    cudaGetSymbolAddress((void**)&sp,   g_s);

    ln_kernel<<<NTOK, 128>>>(z, ln_w, ln_b, zn);
    sgemm_nt<<<dim3((DPROJ + 127) / 128, NTOK / 128), 256>>>(
        zn, ipw, proj, NTOK, DPROJ, EMB, nullptr, nullptr);
    dt_kernel<<<NTOK * NH / 256, 256>>>(proj, dtb, alog, dtp, dAp);
    conv_kernel<<<(int)(((size_t)NTOK * CDIM) / 256), 256>>>(proj, cw, cb, xbc);
    scan_kernel<<<BATCH * NH, 256>>>(xbc, dtp, dAp, Dp, yp);
    gate_rms_kernel<<<NTOK, 256>>>(yp, proj, nw);
    wnorm_kernel<<<EMB / 8, 256>>>(ffv, ffg, sp);
    wc_kernel<<<dim3(DIN / 256, EMB), 256>>>(ffv, sp, opw, wcp);
    sgemm_nt<<<dim3(EMB / 128, NTOK / 128), 256>>>(
        yp, wcp, out, NTOK, EMB, DIN, ffb, z);
}

// round 3
// speedup vs baseline: 1.6904x; 1.6904x over previous
#include <cuda_runtime.h>
#include <math.h>

#define EMB     512
#define DIN     1024
#define DSTATE  128
#define NH      16
#define HDIM    64
#define CDIM    1280
#define DPROJ   2320
#define BATCH   32
#define SEQ     2048
#define NTOK    (BATCH * SEQ)
#define EPSN    1e-5f

// ---------------- scratch (device globals; no runtime allocation) ----------------
static __device__ float g_zn  [(size_t)NTOK * EMB];
static __device__ float g_proj[(size_t)NTOK * DPROJ];
static __device__ float g_xbc [(size_t)NTOK * CDIM];
static __device__ float g_dt  [(size_t)NTOK * NH];
static __device__ float g_dA  [(size_t)NTOK * NH];
static __device__ float g_y   [(size_t)NTOK * DIN];
static __device__ float g_wc  [EMB * DIN];
static __device__ float g_s   [EMB];

// ---------------- LayerNorm over EMB=512 ----------------
__global__ void ln_kernel(const float* __restrict__ z, const float* __restrict__ w,
                          const float* __restrict__ b, float* __restrict__ out)
{
    const int row = blockIdx.x;
    const int tid = threadIdx.x;  // 128 threads, 4 floats each
    float4 v = ((const float4*)(z + (size_t)row * EMB))[tid];
    float s  = v.x + v.y + v.z + v.w;
    float sq = v.x*v.x + v.y*v.y + v.z*v.z + v.w*v.w;
#pragma unroll
    for (int m = 16; m; m >>= 1) {
        s  += __shfl_xor_sync(0xffffffffu, s,  m);
        sq += __shfl_xor_sync(0xffffffffu, sq, m);
    }
    __shared__ float sh[8];
    if ((tid & 31) == 0) { sh[tid >> 5] = s; sh[4 + (tid >> 5)] = sq; }
    __syncthreads();
    s  = sh[0] + sh[1] + sh[2] + sh[3];
    sq = sh[4] + sh[5] + sh[6] + sh[7];
    const float mean = s * (1.f / EMB);
    const float var  = sq * (1.f / EMB) - mean * mean;
    const float r    = rsqrtf(var + EPSN);
    float4 w4 = ((const float4*)w)[tid];
    float4 b4 = ((const float4*)b)[tid];
    float4 o;
    o.x = (v.x - mean) * r * w4.x + b4.x;
    o.y = (v.y - mean) * r * w4.y + b4.y;
    o.z = (v.z - mean) * r * w4.z + b4.z;
    o.w = (v.w - mean) * r * w4.w + b4.w;
    ((float4*)(out + (size_t)row * EMB))[tid] = o;
}

// ---------------- TF32 tensor-core GEMM: C[M,N] = A[M,K]*B[N,K]^T (+bias +resid) ----------------
// 128x128 tile, BK=16, 256 threads = 8 warps (2x4), warp tile 64x32,
// mma.sync.m16n8k8 tf32, fp32 accumulate. Global->register prefetch.
// M % 128 == 0, K % 16 == 0 required. N-edge guarded (N even).
__device__ __forceinline__ unsigned f2tf(float f)
{
    unsigned u;
    asm("cvt.rna.tf32.f32 %0, %1;" : "=r"(u) : "f"(f));
    return u;
}

#define SKW 20   // smem row stride in words (16 + 4 pad): conflict-free fragment reads

__global__ __launch_bounds__(256, 2)
void tgemm_nt(const float* __restrict__ A, const float* __restrict__ B,
              float* __restrict__ C, int M, int N, int K,
              const float* __restrict__ bias, const float* __restrict__ resid)
{
    __shared__ unsigned As[128][SKW];
    __shared__ unsigned Bs[128][SKW];
    const int tid  = threadIdx.x;
    const int bm   = blockIdx.y << 7;
    const int bn   = blockIdx.x << 7;
    const int wid  = tid >> 5;
    const int lane = tid & 31;
    const int wm   = (wid >> 2) << 6;   // 0 | 64
    const int wn   = (wid & 3) << 5;    // 0,32,64,96
    const int g    = lane >> 2;         // 0..7
    const int t    = lane & 3;          // 0..3

    float acc[4][4][4];
#pragma unroll
    for (int mi = 0; mi < 4; mi++)
#pragma unroll
        for (int ni = 0; ni < 4; ni++)
#pragma unroll
            for (int c = 0; c < 4; c++) acc[mi][ni][c] = 0.f;

    const int lr = tid >> 2;        // 0..63
    const int lk = (tid & 3) << 2;  // 0,4,8,12

    float4 pa[2], pb[2];
#pragma unroll
    for (int it = 0; it < 2; it++) {
        const int r = lr + (it << 6);
        pa[it] = *(const float4*)(A + (size_t)(bm + r) * K + lk);
        pb[it] = make_float4(0.f, 0.f, 0.f, 0.f);
        if (bn + r < N)
            pb[it] = *(const float4*)(B + (size_t)(bn + r) * K + lk);
    }

    for (int k0 = 0; k0 < K; k0 += 16) {
#pragma unroll
        for (int it = 0; it < 2; it++) {
            const int r = lr + (it << 6);
            As[r][lk+0] = f2tf(pa[it].x); As[r][lk+1] = f2tf(pa[it].y);
            As[r][lk+2] = f2tf(pa[it].z); As[r][lk+3] = f2tf(pa[it].w);
            Bs[r][lk+0] = f2tf(pb[it].x); Bs[r][lk+1] = f2tf(pb[it].y);
            Bs[r][lk+2] = f2tf(pb[it].z); Bs[r][lk+3] = f2tf(pb[it].w);
        }
        __syncthreads();

        if (k0 + 16 < K) {
#pragma unroll
            for (int it = 0; it < 2; it++) {
                const int r = lr + (it << 6);
                pa[it] = *(const float4*)(A + (size_t)(bm + r) * K + k0 + 16 + lk);
                pb[it] = make_float4(0.f, 0.f, 0.f, 0.f);
                if (bn + r < N)
                    pb[it] = *(const float4*)(B + (size_t)(bn + r) * K + k0 + 16 + lk);
            }
        }

#pragma unroll
        for (int kk = 0; kk < 16; kk += 8) {
            unsigned af[4][4], bf[4][2];
#pragma unroll
            for (int mi = 0; mi < 4; mi++) {
                const int r0 = wm + (mi << 4) + g;
                af[mi][0] = As[r0    ][kk + t];
                af[mi][1] = As[r0 + 8][kk + t];
                af[mi][2] = As[r0    ][kk + t + 4];
                af[mi][3] = As[r0 + 8][kk + t + 4];
            }
#pragma unroll
            for (int ni = 0; ni < 4; ni++) {
                const int n0 = wn + (ni << 3) + g;
                bf[ni][0] = Bs[n0][kk + t];
                bf[ni][1] = Bs[n0][kk + t + 4];
            }
#pragma unroll
            for (int mi = 0; mi < 4; mi++)
#pragma unroll
                for (int ni = 0; ni < 4; ni++) {
                    asm volatile(
                        "mma.sync.aligned.m16n8k8.row.col.f32.tf32.tf32.f32 "
                        "{%0,%1,%2,%3}, {%4,%5,%6,%7}, {%8,%9}, {%0,%1,%2,%3};"
                        : "+f"(acc[mi][ni][0]), "+f"(acc[mi][ni][1]),
                          "+f"(acc[mi][ni][2]), "+f"(acc[mi][ni][3])
                        : "r"(af[mi][0]), "r"(af[mi][1]), "r"(af[mi][2]), "r"(af[mi][3]),
                          "r"(bf[ni][0]), "r"(bf[ni][1]));
                }
        }
        __syncthreads();
    }

    // epilogue: c0,c1 -> (row, col..col+1); c2,c3 -> (row+8, col..col+1)
#pragma unroll
    for (int mi = 0; mi < 4; mi++) {
        const int row = bm + wm + (mi << 4) + g;
#pragma unroll
        for (int ni = 0; ni < 4; ni++) {
            const int col = bn + wn + (ni << 3) + (t << 1);
            if (col < N) {   // N even => col+1 valid whenever col is
                float2 v0 = make_float2(acc[mi][ni][0], acc[mi][ni][1]);
                float2 v1 = make_float2(acc[mi][ni][2], acc[mi][ni][3]);
                if (bias) {
                    v0.x += bias[col]; v0.y += bias[col + 1];
                    v1.x += bias[col]; v1.y += bias[col + 1];
                }
                const size_t o0 = (size_t)row * N + col;
                const size_t o1 = (size_t)(row + 8) * N + col;
                if (resid) {
                    const float2 r0 = *(const float2*)(resid + o0);
                    const float2 r1 = *(const float2*)(resid + o1);
                    v0.x += r0.x; v0.y += r0.y; v1.x += r1.x; v1.y += r1.y;
                }
                *(float2*)(C + o0) = v0;
                *(float2*)(C + o1) = v1;
            }
        }
    }
}

// ---------------- dt = softplus(proj[..,2304+h] + dt_bias); dA = exp(dt * -exp(A_log)) ----------------
__global__ void dt_kernel(const float* __restrict__ proj, const float* __restrict__ dtb,
                          const float* __restrict__ alog, float* __restrict__ dt,
                          float* __restrict__ dA)
{
    const int i = blockIdx.x * 256 + threadIdx.x;
    if (i >= NTOK * NH) return;
    const int h   = i & (NH - 1);
    const int row = i >> 4;
    const float v = proj[(size_t)row * DPROJ + (DIN + CDIM) + h] + dtb[h];
    const float d = (v > 20.f) ? v : log1pf(expf(v));
    dt[i] = d;
    dA[i] = expf(-d * expf(alog[h]));
}

// ---------------- depthwise causal conv (width 4) + bias + SiLU ----------------
__global__ void conv_kernel(const float* __restrict__ proj, const float* __restrict__ cw,
                            const float* __restrict__ cb, float* __restrict__ xbc)
{
    const int idx = blockIdx.x * 256 + threadIdx.x;
    const int c   = idx % CDIM;
    const int bt  = idx / CDIM;
    const int t   = bt & (SEQ - 1);
    float acc = cb[c];
#pragma unroll
    for (int d = 0; d < 4; d++) {
        if (t - d >= 0)
            acc = fmaf(proj[(size_t)(bt - d) * DPROJ + DIN + c], cw[c * 4 + (3 - d)], acc);
    }
    xbc[idx] = acc / (1.f + expf(-acc));
}

// ---------------- SSM scan: one CTA per (batch, head) ----------------
__global__ __launch_bounds__(256, 4)
void scan_kernel(const float* __restrict__ xbc, const float* __restrict__ dt,
                 const float* __restrict__ dA, const float* __restrict__ Dp,
                 float* __restrict__ y)
{
    const int b   = blockIdx.x >> 4;
    const int hd  = blockIdx.x & 15;
    const int tid = threadIdx.x;
    const int p4  = tid >> 4;
    const int ng  = tid & 15;
    __shared__ float sB[2][DSTATE], sC[2][DSTATE], sx[2][HDIM];
    __shared__ float sdt[2], sdA[2];

    float h[4][8];
#pragma unroll
    for (int i = 0; i < 4; i++)
#pragma unroll
        for (int j = 0; j < 8; j++) h[i][j] = 0.f;

    const float  Dh = Dp[hd];
    const size_t rb = (size_t)b * SEQ;
    {
        const float* p = xbc + rb * CDIM;
        if (tid < 128) { sB[0][tid] = p[DIN + tid]; sC[0][tid] = p[DIN + DSTATE + tid]; }
        if (tid < 64)  sx[0][tid] = p[hd * HDIM + tid];
        if (tid == 0)  { sdt[0] = dt[rb * NH + hd]; sdA[0] = dA[rb * NH + hd]; }
    }
    __syncthreads();

    for (int t = 0; t < SEQ; t++) {
        const int cur = t & 1, nxt = cur ^ 1;
        if (t + 1 < SEQ) {
            const float* p = xbc + (rb + t + 1) * CDIM;
            if (tid < 128) { sB[nxt][tid] = p[DIN + tid]; sC[nxt][tid] = p[DIN + DSTATE + tid]; }
            if (tid < 64)  sx[nxt][tid] = p[hd * HDIM + tid];
            if (tid == 0)  { sdt[nxt] = dt[(rb + t + 1) * NH + hd];
                             sdA[nxt] = dA[(rb + t + 1) * NH + hd]; }
        }
        const float dtv = sdt[cur], dAv = sdA[cur];
        const float4 xv = *(const float4*)&sx[cur][p4 << 2];
        const float c0 = dtv * xv.x, c1 = dtv * xv.y, c2 = dtv * xv.z, c3 = dtv * xv.w;
        float a0 = 0.f, a1 = 0.f, a2 = 0.f, a3 = 0.f;
#pragma unroll
        for (int j = 0; j < 8; j++) {
            const int   n  = ng + (j << 4);
            const float Bv = sB[cur][n];
            const float Cv = sC[cur][n];
            h[0][j] = fmaf(h[0][j], dAv, c0 * Bv);  a0 = fmaf(h[0][j], Cv, a0);
            h[1][j] = fmaf(h[1][j], dAv, c1 * Bv);  a1 = fmaf(h[1][j], Cv, a1);
            h[2][j] = fmaf(h[2][j], dAv, c2 * Bv);  a2 = fmaf(h[2][j], Cv, a2);
            h[3][j] = fmaf(h[3][j], dAv, c3 * Bv);  a3 = fmaf(h[3][j], Cv, a3);
        }
#pragma unroll
        for (int m = 1; m < 16; m <<= 1) {
            a0 += __shfl_xor_sync(0xffffffffu, a0, m);
            a1 += __shfl_xor_sync(0xffffffffu, a1, m);
            a2 += __shfl_xor_sync(0xffffffffu, a2, m);
            a3 += __shfl_xor_sync(0xffffffffu, a3, m);
        }
        if (ng == 0) {
            float4 o;
            o.x = a0 + xv.x * Dh;
            o.y = a1 + xv.y * Dh;
            o.z = a2 + xv.z * Dh;
            o.w = a3 + xv.w * Dh;
            *(float4*)(y + (rb + t) * (size_t)DIN + hd * HDIM + (p4 << 2)) = o;
        }
        __syncthreads();
    }
}

// ---------------- y = y*silu(zg); RMSNorm over DIN (in place) ----------------
__global__ void gate_rms_kernel(float* __restrict__ y, const float* __restrict__ proj,
                                const float* __restrict__ nw)
{
    const int row = blockIdx.x;
    const int tid = threadIdx.x;
    float4 yv = *(float4*)(y + (size_t)row * DIN + (tid << 2));
    float4 zg = *(const float4*)(proj + (size_t)row * DPROJ + (tid << 2));
    float4 g;
    g.x = yv.x * (zg.x / (1.f + expf(-zg.x)));
    g.y = yv.y * (zg.y / (1.f + expf(-zg.y)));
    g.z = yv.z * (zg.z / (1.f + expf(-zg.z)));
    g.w = yv.w * (zg.w / (1.f + expf(-zg.w)));
    float sq = g.x*g.x + g.y*g.y + g.z*g.z + g.w*g.w;
#pragma unroll
    for (int m = 16; m; m >>= 1) sq += __shfl_xor_sync(0xffffffffu, sq, m);
    __shared__ float sh[8];
    if ((tid & 31) == 0) sh[tid >> 5] = sq;
    __syncthreads();
    const float tot = sh[0] + sh[1] + sh[2] + sh[3] + sh[4] + sh[5] + sh[6] + sh[7];
    const float r   = rsqrtf(tot * (1.f / DIN) + EPSN);
    float4 w4 = ((const float4*)nw)[tid];
    float4 o;
    o.x = g.x * r * w4.x; o.y = g.y * r * w4.y; o.z = g.z * r * w4.z; o.w = g.w * r * w4.w;
    *(float4*)(y + (size_t)row * DIN + (tid << 2)) = o;
}

// ---------------- s[e] = ff_g[e] / ||ff_v[e,:]|| ----------------
__global__ void wnorm_kernel(const float* __restrict__ fv, const float* __restrict__ fg,
                             float* __restrict__ s)
{
    const int e   = blockIdx.x * 8 + (threadIdx.x >> 5);
    const int lid = threadIdx.x & 31;
    const float* rp = fv + (size_t)e * EMB;
    float sq = 0.f;
    for (int k = lid; k < EMB; k += 32) { const float v = rp[k]; sq += v * v; }
#pragma unroll
    for (int m = 16; m; m >>= 1) sq += __shfl_xor_sync(0xffffffffu, sq, m);
    if (lid == 0) s[e] = fg[e] / sqrtf(sq);
}

// ---------------- Wc[e,j] = s[e] * sum_k ff_v[e,k] * out_proj_w[k,j] ----------------
__global__ void wc_kernel(const float* __restrict__ fv, const float* __restrict__ s,
                          const float* __restrict__ op, float* __restrict__ wc)
{
    const int j = blockIdx.x * 256 + threadIdx.x;
    const int e = blockIdx.y;
    const float* fr = fv + (size_t)e * EMB;
    float acc = 0.f;
#pragma unroll 4
    for (int k = 0; k < EMB; k++)
        acc = fmaf(fr[k], op[(size_t)k * DIN + j], acc);
    wc[(size_t)e * DIN + j] = acc * s[e];
}

// ---------------- launch ----------------
extern "C" void kernel_launch(void* const* d_in, const int* in_sizes, int n_in,
                              void* d_out, int out_size)
{
    const float* z    = (const float*)d_in[0];
    const float* ln_w = (const float*)d_in[1];
    const float* ln_b = (const float*)d_in[2];
    const float* ipw  = (const float*)d_in[3];
    const float* cw   = (const float*)d_in[4];
    const float* cb   = (const float*)d_in[5];
    const float* dtb  = (const float*)d_in[6];
    const float* alog = (const float*)d_in[7];
    const float* Dp   = (const float*)d_in[8];
    const float* nw   = (const float*)d_in[9];
    const float* opw  = (const float*)d_in[10];
    const float* ffv  = (const float*)d_in[11];
    const float* ffg  = (const float*)d_in[12];
    const float* ffb  = (const float*)d_in[13];
    float* out = (float*)d_out;
    (void)in_sizes; (void)n_in; (void)out_size;

    float *zn, *proj, *xbc, *dtp, *dAp, *yp, *wcp, *sp;
    cudaGetSymbolAddress((void**)&zn,   g_zn);
    cudaGetSymbolAddress((void**)&proj, g_proj);
    cudaGetSymbolAddress((void**)&xbc,  g_xbc);
    cudaGetSymbolAddress((void**)&dtp,  g_dt);
    cudaGetSymbolAddress((void**)&dAp,  g_dA);
    cudaGetSymbolAddress((void**)&yp,   g_y);
    cudaGetSymbolAddress((void**)&wcp,  g_wc);
    cudaGetSymbolAddress((void**)&sp,   g_s);

    ln_kernel<<<NTOK, 128>>>(z, ln_w, ln_b, zn);
    tgemm_nt<<<dim3((DPROJ + 127) / 128, NTOK / 128), 256>>>(
        zn, ipw, proj, NTOK, DPROJ, EMB, nullptr, nullptr);
    dt_kernel<<<NTOK * NH / 256, 256>>>(proj, dtb, alog, dtp, dAp);
    conv_kernel<<<(int)(((size_t)NTOK * CDIM) / 256), 256>>>(proj, cw, cb, xbc);
    scan_kernel<<<BATCH * NH, 256>>>(xbc, dtp, dAp, Dp, yp);
    gate_rms_kernel<<<NTOK, 256>>>(yp, proj, nw);
    wnorm_kernel<<<EMB / 8, 256>>>(ffv, ffg, sp);
    wc_kernel<<<dim3(DIN / 256, EMB), 256>>>(ffv, sp, opw, wcp);
    tgemm_nt<<<dim3(EMB / 128, NTOK / 128), 256>>>(
        yp, wcp, out, NTOK, EMB, DIN, ffb, z);
}

// round 5
// speedup vs baseline: 1.6928x; 1.0014x over previous
#include <cuda_runtime.h>
#include <math.h>

#define EMB     512
#define DIN     1024
#define DSTATE  128
#define NH      16
#define HDIM    64
#define CDIM    1280
#define DPROJ   2320
#define BATCH   32
#define SEQ     2048
#define NTOK    (BATCH * SEQ)
#define EPSN    1e-5f

// ---------------- scratch (device globals; no runtime allocation) ----------------
static __device__ float g_zn  [(size_t)NTOK * EMB];
static __device__ float g_proj[(size_t)NTOK * DPROJ];
static __device__ float g_xbc [(size_t)NTOK * CDIM];
static __device__ float g_dt  [(size_t)NTOK * NH];
static __device__ float g_dA  [(size_t)NTOK * NH];
static __device__ float g_y   [(size_t)NTOK * DIN];
static __device__ float g_wc  [EMB * DIN];
static __device__ float g_s   [EMB];

// ---------------- LayerNorm over EMB=512 ----------------
__global__ void ln_kernel(const float* __restrict__ z, const float* __restrict__ w,
                          const float* __restrict__ b, float* __restrict__ out)
{
    const int row = blockIdx.x;
    const int tid = threadIdx.x;  // 128 threads, 4 floats each
    float4 v = ((const float4*)(z + (size_t)row * EMB))[tid];
    float s  = v.x + v.y + v.z + v.w;
    float sq = v.x*v.x + v.y*v.y + v.z*v.z + v.w*v.w;
#pragma unroll
    for (int m = 16; m; m >>= 1) {
        s  += __shfl_xor_sync(0xffffffffu, s,  m);
        sq += __shfl_xor_sync(0xffffffffu, sq, m);
    }
    __shared__ float sh[8];
    if ((tid & 31) == 0) { sh[tid >> 5] = s; sh[4 + (tid >> 5)] = sq; }
    __syncthreads();
    s  = sh[0] + sh[1] + sh[2] + sh[3];
    sq = sh[4] + sh[5] + sh[6] + sh[7];
    const float mean = s * (1.f / EMB);
    const float var  = sq * (1.f / EMB) - mean * mean;
    const float r    = rsqrtf(var + EPSN);
    float4 w4 = ((const float4*)w)[tid];
    float4 b4 = ((const float4*)b)[tid];
    float4 o;
    o.x = (v.x - mean) * r * w4.x + b4.x;
    o.y = (v.y - mean) * r * w4.y + b4.y;
    o.z = (v.z - mean) * r * w4.z + b4.z;
    o.w = (v.w - mean) * r * w4.w + b4.w;
    ((float4*)(out + (size_t)row * EMB))[tid] = o;
}

// ---------------- TF32 tensor-core GEMM: C[M,N] = A[M,K]*B[N,K]^T (+bias +resid) ----------------
// 128x128 tile, BK=16, 256 threads = 8 warps (2x4), warp tile 64x32,
// mma.sync.m16n8k8 tf32, fp32 accumulate. Double-buffered smem, one sync/tile,
// global->register prefetch overlapped with MMA compute.
// M % 128 == 0, K % 16 == 0 required. N-edge guarded (N even).
__device__ __forceinline__ unsigned f2tf(float f)
{
    unsigned u;
    asm("cvt.rna.tf32.f32 %0, %1;" : "=r"(u) : "f"(f));
    return u;
}

#define SKW 20   // smem row stride in words (16 + 4 pad): conflict-free fragment reads

__global__ __launch_bounds__(256)
void tgemm_nt(const float* __restrict__ A, const float* __restrict__ B,
              float* __restrict__ C, int M, int N, int K,
              const float* __restrict__ bias, const float* __restrict__ resid)
{
    __shared__ unsigned As[2][128][SKW];   // 20 KB x2
    __shared__ unsigned Bs[2][128][SKW];   // 20 KB x2
    const int tid  = threadIdx.x;
    const int bm   = blockIdx.y << 7;
    const int bn   = blockIdx.x << 7;
    const int wid  = tid >> 5;
    const int lane = tid & 31;
    const int wm   = (wid >> 2) << 6;   // 0 | 64
    const int wn   = (wid & 3) << 5;    // 0,32,64,96
    const int g    = lane >> 2;         // 0..7
    const int t    = lane & 3;          // 0..3

    float acc[4][4][4];
#pragma unroll
    for (int mi = 0; mi < 4; mi++)
#pragma unroll
        for (int ni = 0; ni < 4; ni++)
#pragma unroll
            for (int c = 0; c < 4; c++) acc[mi][ni][c] = 0.f;

    const int lr = tid >> 2;        // 0..63
    const int lk = (tid & 3) << 2;  // 0,4,8,12

    // load tile 0 into registers, stage into buffer 0
    float4 pa[2], pb[2];
#pragma unroll
    for (int it = 0; it < 2; it++) {
        const int r = lr + (it << 6);
        pa[it] = *(const float4*)(A + (size_t)(bm + r) * K + lk);
        pb[it] = make_float4(0.f, 0.f, 0.f, 0.f);
        if (bn + r < N)
            pb[it] = *(const float4*)(B + (size_t)(bn + r) * K + lk);
    }
#pragma unroll
    for (int it = 0; it < 2; it++) {
        const int r = lr + (it << 6);
        As[0][r][lk+0] = f2tf(pa[it].x); As[0][r][lk+1] = f2tf(pa[it].y);
        As[0][r][lk+2] = f2tf(pa[it].z); As[0][r][lk+3] = f2tf(pa[it].w);
        Bs[0][r][lk+0] = f2tf(pb[it].x); Bs[0][r][lk+1] = f2tf(pb[it].y);
        Bs[0][r][lk+2] = f2tf(pb[it].z); Bs[0][r][lk+3] = f2tf(pb[it].w);
    }
    __syncthreads();

    for (int k0 = 0; k0 < K; k0 += 16) {
        const int cur = (k0 >> 4) & 1;
        const bool more = (k0 + 16 < K);

        // prefetch next tile into registers (latency hidden by MMA block below)
        if (more) {
#pragma unroll
            for (int it = 0; it < 2; it++) {
                const int r = lr + (it << 6);
                pa[it] = *(const float4*)(A + (size_t)(bm + r) * K + k0 + 16 + lk);
                pb[it] = make_float4(0.f, 0.f, 0.f, 0.f);
                if (bn + r < N)
                    pb[it] = *(const float4*)(B + (size_t)(bn + r) * K + k0 + 16 + lk);
            }
        }

        // compute on current buffer
#pragma unroll
        for (int kk = 0; kk < 16; kk += 8) {
            unsigned af[4][4], bf[4][2];
#pragma unroll
            for (int mi = 0; mi < 4; mi++) {
                const int r0 = wm + (mi << 4) + g;
                af[mi][0] = As[cur][r0    ][kk + t];
                af[mi][1] = As[cur][r0 + 8][kk + t];
                af[mi][2] = As[cur][r0    ][kk + t + 4];
                af[mi][3] = As[cur][r0 + 8][kk + t + 4];
            }
#pragma unroll
            for (int ni = 0; ni < 4; ni++) {
                const int n0 = wn + (ni << 3) + g;
                bf[ni][0] = Bs[cur][n0][kk + t];
                bf[ni][1] = Bs[cur][n0][kk + t + 4];
            }
#pragma unroll
            for (int mi = 0; mi < 4; mi++)
#pragma unroll
                for (int ni = 0; ni < 4; ni++) {
                    asm volatile(
                        "mma.sync.aligned.m16n8k8.row.col.f32.tf32.tf32.f32 "
                        "{%0,%1,%2,%3}, {%4,%5,%6,%7}, {%8,%9}, {%0,%1,%2,%3};"
                        : "+f"(acc[mi][ni][0]), "+f"(acc[mi][ni][1]),
                          "+f"(acc[mi][ni][2]), "+f"(acc[mi][ni][3])
                        : "r"(af[mi][0]), "r"(af[mi][1]), "r"(af[mi][2]), "r"(af[mi][3]),
                          "r"(bf[ni][0]), "r"(bf[ni][1]));
                }
        }

        // stage next tile into the other buffer (no hazard: peers read 'cur')
        if (more) {
            const int nb = cur ^ 1;
#pragma unroll
            for (int it = 0; it < 2; it++) {
                const int r = lr + (it << 6);
                As[nb][r][lk+0] = f2tf(pa[it].x); As[nb][r][lk+1] = f2tf(pa[it].y);
                As[nb][r][lk+2] = f2tf(pa[it].z); As[nb][r][lk+3] = f2tf(pa[it].w);
                Bs[nb][r][lk+0] = f2tf(pb[it].x); Bs[nb][r][lk+1] = f2tf(pb[it].y);
                Bs[nb][r][lk+2] = f2tf(pb[it].z); Bs[nb][r][lk+3] = f2tf(pb[it].w);
            }
        }
        __syncthreads();
    }

    // epilogue: c0,c1 -> (row, col..col+1); c2,c3 -> (row+8, col..col+1)
#pragma unroll
    for (int mi = 0; mi < 4; mi++) {
        const int row = bm + wm + (mi << 4) + g;
#pragma unroll
        for (int ni = 0; ni < 4; ni++) {
            const int col = bn + wn + (ni << 3) + (t << 1);
            if (col < N) {   // N even => col+1 valid whenever col is
                float2 v0 = make_float2(acc[mi][ni][0], acc[mi][ni][1]);
                float2 v1 = make_float2(acc[mi][ni][2], acc[mi][ni][3]);
                if (bias) {
                    v0.x += bias[col]; v0.y += bias[col + 1];
                    v1.x += bias[col]; v1.y += bias[col + 1];
                }
                const size_t o0 = (size_t)row * N + col;
                const size_t o1 = (size_t)(row + 8) * N + col;
                if (resid) {
                    const float2 r0 = *(const float2*)(resid + o0);
                    const float2 r1 = *(const float2*)(resid + o1);
                    v0.x += r0.x; v0.y += r0.y; v1.x += r1.x; v1.y += r1.y;
                }
                *(float2*)(C + o0) = v0;
                *(float2*)(C + o1) = v1;
            }
        }
    }
}

// ---------------- dt = softplus(proj[..,2304+h] + dt_bias); dA = exp(dt * -exp(A_log)) ----------------
__global__ void dt_kernel(const float* __restrict__ proj, const float* __restrict__ dtb,
                          const float* __restrict__ alog, float* __restrict__ dt,
                          float* __restrict__ dA)
{
    const int i = blockIdx.x * 256 + threadIdx.x;
    if (i >= NTOK * NH) return;
    const int h   = i & (NH - 1);
    const int row = i >> 4;
    const float v = proj[(size_t)row * DPROJ + (DIN + CDIM) + h] + dtb[h];
    const float d = (v > 20.f) ? v : log1pf(expf(v));
    dt[i] = d;
    dA[i] = expf(-d * expf(alog[h]));
}

// ---------------- depthwise causal conv (width 4) + bias + SiLU ----------------
__global__ void conv_kernel(const float* __restrict__ proj, const float* __restrict__ cw,
                            const float* __restrict__ cb, float* __restrict__ xbc)
{
    const int idx = blockIdx.x * 256 + threadIdx.x;
    const int c   = idx % CDIM;
    const int bt  = idx / CDIM;
    const int t   = bt & (SEQ - 1);
    float acc = cb[c];
#pragma unroll
    for (int d = 0; d < 4; d++) {
        if (t - d >= 0)
            acc = fmaf(proj[(size_t)(bt - d) * DPROJ + DIN + c], cw[c * 4 + (3 - d)], acc);
    }
    xbc[idx] = acc / (1.f + expf(-acc));
}

// ---------------- SSM scan: one CTA per (batch, head) ----------------
__global__ __launch_bounds__(256, 4)
void scan_kernel(const float* __restrict__ xbc, const float* __restrict__ dt,
                 const float* __restrict__ dA, const float* __restrict__ Dp,
                 float* __restrict__ y)
{
    const int b   = blockIdx.x >> 4;
    const int hd  = blockIdx.x & 15;
    const int tid = threadIdx.x;
    const int p4  = tid >> 4;
    const int ng  = tid & 15;
    __shared__ float sB[2][DSTATE], sC[2][DSTATE], sx[2][HDIM];
    __shared__ float sdt[2], sdA[2];

    float h[4][8];
#pragma unroll
    for (int i = 0; i < 4; i++)
#pragma unroll
        for (int j = 0; j < 8; j++) h[i][j] = 0.f;

    const float  Dh = Dp[hd];
    const size_t rb = (size_t)b * SEQ;
    {
        const float* p = xbc + rb * CDIM;
        if (tid < 128) { sB[0][tid] = p[DIN + tid]; sC[0][tid] = p[DIN + DSTATE + tid]; }
        if (tid < 64)  sx[0][tid] = p[hd * HDIM + tid];
        if (tid == 0)  { sdt[0] = dt[rb * NH + hd]; sdA[0] = dA[rb * NH + hd]; }
    }
    __syncthreads();

    for (int t = 0; t < SEQ; t++) {
        const int cur = t & 1, nxt = cur ^ 1;
        if (t + 1 < SEQ) {
            const float* p = xbc + (rb + t + 1) * CDIM;
            if (tid < 128) { sB[nxt][tid] = p[DIN + tid]; sC[nxt][tid] = p[DIN + DSTATE + tid]; }
            if (tid < 64)  sx[nxt][tid] = p[hd * HDIM + tid];
            if (tid == 0)  { sdt[nxt] = dt[(rb + t + 1) * NH + hd];
                             sdA[nxt] = dA[(rb + t + 1) * NH + hd]; }
        }
        const float dtv = sdt[cur], dAv = sdA[cur];
        const float4 xv = *(const float4*)&sx[cur][p4 << 2];
        const float c0 = dtv * xv.x, c1 = dtv * xv.y, c2 = dtv * xv.z, c3 = dtv * xv.w;
        float a0 = 0.f, a1 = 0.f, a2 = 0.f, a3 = 0.f;
#pragma unroll
        for (int j = 0; j < 8; j++) {
            const int   n  = ng + (j << 4);
            const float Bv = sB[cur][n];
            const float Cv = sC[cur][n];
            h[0][j] = fmaf(h[0][j], dAv, c0 * Bv);  a0 = fmaf(h[0][j], Cv, a0);
            h[1][j] = fmaf(h[1][j], dAv, c1 * Bv);  a1 = fmaf(h[1][j], Cv, a1);
            h[2][j] = fmaf(h[2][j], dAv, c2 * Bv);  a2 = fmaf(h[2][j], Cv, a2);
            h[3][j] = fmaf(h[3][j], dAv, c3 * Bv);  a3 = fmaf(h[3][j], Cv, a3);
        }
#pragma unroll
        for (int m = 1; m < 16; m <<= 1) {
            a0 += __shfl_xor_sync(0xffffffffu, a0, m);
            a1 += __shfl_xor_sync(0xffffffffu, a1, m);
            a2 += __shfl_xor_sync(0xffffffffu, a2, m);
            a3 += __shfl_xor_sync(0xffffffffu, a3, m);
        }
        if (ng == 0) {
            float4 o;
            o.x = a0 + xv.x * Dh;
            o.y = a1 + xv.y * Dh;
            o.z = a2 + xv.z * Dh;
            o.w = a3 + xv.w * Dh;
            *(float4*)(y + (rb + t) * (size_t)DIN + hd * HDIM + (p4 << 2)) = o;
        }
        __syncthreads();
    }
}

// ---------------- y = y*silu(zg); RMSNorm over DIN (in place) ----------------
__global__ void gate_rms_kernel(float* __restrict__ y, const float* __restrict__ proj,
                                const float* __restrict__ nw)
{
    const int row = blockIdx.x;
    const int tid = threadIdx.x;
    float4 yv = *(float4*)(y + (size_t)row * DIN + (tid << 2));
    float4 zg = *(const float4*)(proj + (size_t)row * DPROJ + (tid << 2));
    float4 g;
    g.x = yv.x * (zg.x / (1.f + expf(-zg.x)));
    g.y = yv.y * (zg.y / (1.f + expf(-zg.y)));
    g.z = yv.z * (zg.z / (1.f + expf(-zg.z)));
    g.w = yv.w * (zg.w / (1.f + expf(-zg.w)));
    float sq = g.x*g.x + g.y*g.y + g.z*g.z + g.w*g.w;
#pragma unroll
    for (int m = 16; m; m >>= 1) sq += __shfl_xor_sync(0xffffffffu, sq, m);
    __shared__ float sh[8];
    if ((tid & 31) == 0) sh[tid >> 5] = sq;
    __syncthreads();
    const float tot = sh[0] + sh[1] + sh[2] + sh[3] + sh[4] + sh[5] + sh[6] + sh[7];
    const float r   = rsqrtf(tot * (1.f / DIN) + EPSN);
    float4 w4 = ((const float4*)nw)[tid];
    float4 o;
    o.x = g.x * r * w4.x; o.y = g.y * r * w4.y; o.z = g.z * r * w4.z; o.w = g.w * r * w4.w;
    *(float4*)(y + (size_t)row * DIN + (tid << 2)) = o;
}

// ---------------- s[e] = ff_g[e] / ||ff_v[e,:]|| ----------------
__global__ void wnorm_kernel(const float* __restrict__ fv, const float* __restrict__ fg,
                             float* __restrict__ s)
{
    const int e   = blockIdx.x * 8 + (threadIdx.x >> 5);
    const int lid = threadIdx.x & 31;
    const float* rp = fv + (size_t)e * EMB;
    float sq = 0.f;
    for (int k = lid; k < EMB; k += 32) { const float v = rp[k]; sq += v * v; }
#pragma unroll
    for (int m = 16; m; m >>= 1) sq += __shfl_xor_sync(0xffffffffu, sq, m);
    if (lid == 0) s[e] = fg[e] / sqrtf(sq);
}

// ---------------- Wc[e,j] = s[e] * sum_k ff_v[e,k] * out_proj_w[k,j] ----------------
__global__ void wc_kernel(const float* __restrict__ fv, const float* __restrict__ s,
                          const float* __restrict__ op, float* __restrict__ wc)
{
    const int j = blockIdx.x * 256 + threadIdx.x;
    const int e = blockIdx.y;
    const float* fr = fv + (size_t)e * EMB;
    float acc = 0.f;
#pragma unroll 4
    for (int k = 0; k < EMB; k++)
        acc = fmaf(fr[k], op[(size_t)k * DIN + j], acc);
    wc[(size_t)e * DIN + j] = acc * s[e];
}

// ---------------- launch ----------------
extern "C" void kernel_launch(void* const* d_in, const int* in_sizes, int n_in,
                              void* d_out, int out_size)
{
    const float* z    = (const float*)d_in[0];
    const float* ln_w = (const float*)d_in[1];
    const float* ln_b = (const float*)d_in[2];
    const float* ipw  = (const float*)d_in[3];
    const float* cw   = (const float*)d_in[4];
    const float* cb   = (const float*)d_in[5];
    const float* dtb  = (const float*)d_in[6];
    const float* alog = (const float*)d_in[7];
    const float* Dp   = (const float*)d_in[8];
    const float* nw   = (const float*)d_in[9];
    const float* opw  = (const float*)d_in[10];
    const float* ffv  = (const float*)d_in[11];
    const float* ffg  = (const float*)d_in[12];
    const float* ffb  = (const float*)d_in[13];
    float* out = (float*)d_out;
    (void)in_sizes; (void)n_in; (void)out_size;

    float *zn, *proj, *xbc, *dtp, *dAp, *yp, *wcp, *sp;
    cudaGetSymbolAddress((void**)&zn,   g_zn);
    cudaGetSymbolAddress((void**)&proj, g_proj);
    cudaGetSymbolAddress((void**)&xbc,  g_xbc);
    cudaGetSymbolAddress((void**)&dtp,  g_dt);
    cudaGetSymbolAddress((void**)&dAp,  g_dA);
    cudaGetSymbolAddress((void**)&yp,   g_y);
    cudaGetSymbolAddress((void**)&wcp,  g_wc);
    cudaGetSymbolAddress((void**)&sp,   g_s);

    ln_kernel<<<NTOK, 128>>>(z, ln_w, ln_b, zn);
    tgemm_nt<<<dim3((DPROJ + 127) / 128, NTOK / 128), 256>>>(
        zn, ipw, proj, NTOK, DPROJ, EMB, nullptr, nullptr);
    dt_kernel<<<NTOK * NH / 256, 256>>>(proj, dtb, alog, dtp, dAp);
    conv_kernel<<<(int)(((size_t)NTOK * CDIM) / 256), 256>>>(proj, cw, cb, xbc);
    scan_kernel<<<BATCH * NH, 256>>>(xbc, dtp, dAp, Dp, yp);
    gate_rms_kernel<<<NTOK, 256>>>(yp, proj, nw);
    wnorm_kernel<<<EMB / 8, 256>>>(ffv, ffg, sp);
    wc_kernel<<<dim3(DIN / 256, EMB), 256>>>(ffv, sp, opw, wcp);
    tgemm_nt<<<dim3(EMB / 128, NTOK / 128), 256>>>(
        yp, wcp, out, NTOK, EMB, DIN, ffb, z);
}